// round 1
// baseline (speedup 1.0000x reference)
#include <cuda_runtime.h>

#define B_ 32
#define C_ 512
#define L_ 2048
#define F_ 1025
#define NE 8
#define ROWS_PER_BLK 8
#define GROUPS (C_/ROWS_PER_BLK)  // 64

// ---------------- scratch (static device allocs only) ----------------
__device__ float2 g_tw1024[1024];     // e^{-2*pi*i*j/1024}
__device__ float2 g_tw2048[1025];     // e^{-2*pi*i*f/2048}
__device__ float  g_mean[B_*L_];
__device__ float  g_rstd[B_*L_];
__device__ float  g_partial[B_*GROUPS*F_];
__device__ float  g_w[B_*F_];

// base-4 digit reversal of 5 digits (1024 points)
__device__ __forceinline__ int dr4(int k){
  return ((k&3)<<8)|(((k>>2)&3)<<6)|(((k>>4)&3)<<4)|(((k>>6)&3)<<2)|((k>>8)&3);
}
#define ZIDX(i) ((i) + ((i)>>4))   // shared padding: <=2-way conflicts all stages

__device__ __forceinline__ float2 cmul(float2 a, float2 w){
  return make_float2(a.x*w.x - a.y*w.y, a.x*w.y + a.y*w.x);
}
__device__ __forceinline__ float2 cmulc(float2 a, float2 w){ // a * conj(w)
  return make_float2(a.x*w.x + a.y*w.y, a.y*w.x - a.x*w.y);
}

// ---------------- K0: twiddle tables ----------------
__global__ void k_twiddle(){
  int j = blockIdx.x*blockDim.x + threadIdx.x;
  if (j < 1024){
    double s, c; sincospi(-2.0*(double)j/1024.0, &s, &c);
    g_tw1024[j] = make_float2((float)c, (float)s);
  }
  if (j < 1025){
    double s, c; sincospi(-(double)j/1024.0, &s, &c);
    g_tw2048[j] = make_float2((float)c, (float)s);
  }
}

// ---------------- K1: per-(b,l) stats over channels ----------------
__global__ __launch_bounds__(256) void k_stats(const float* __restrict__ x){
  int l = blockIdx.x*256 + threadIdx.x;
  int b = blockIdx.y;
  const float* p = x + (size_t)b*C_*L_ + l;
  float s = 0.f, s2 = 0.f;
  #pragma unroll 8
  for (int c = 0; c < C_; c++){
    float v = p[(size_t)c*L_];
    s += v; s2 += v*v;
  }
  float mean = s * (1.0f/C_);
  float var  = (s2 - s*s*(1.0f/C_)) * (1.0f/(C_-1)) + 1e-5f;
  g_mean[b*L_+l] = mean;
  g_rstd[b*L_+l] = rsqrtf(var);
}

// ---------------- FFT helpers (256 threads, 1024 complex points) ----------------
// Forward: radix-4 DIF, natural input -> base-4 digit-reversed output.
__device__ __forceinline__ void fft_fwd(float2* z, const float2* tw, int t){
  #pragma unroll
  for (int m = 256; m >= 1; m >>= 2){
    __syncthreads();
    int tq = t & (m-1);
    int j  = ((t & ~(m-1)) << 2) | tq;
    int i1 = tq * (256/m);
    float2 a = z[ZIDX(j)],     b = z[ZIDX(j+m)];
    float2 c = z[ZIDX(j+2*m)], d = z[ZIDX(j+3*m)];
    float t0x=a.x+c.x, t0y=a.y+c.y, t1x=a.x-c.x, t1y=a.y-c.y;
    float t2x=b.x+d.x, t2y=b.y+d.y, t3x=b.x-d.x, t3y=b.y-d.y;
    float2 y0 = make_float2(t0x+t2x, t0y+t2y);
    float2 y2 = make_float2(t0x-t2x, t0y-t2y);
    float2 y1 = make_float2(t1x+t3y, t1y-t3x);   // t1 - i*t3
    float2 y3 = make_float2(t1x-t3y, t1y+t3x);   // t1 + i*t3
    float2 w1 = tw[i1], w2 = tw[2*i1], w3 = tw[3*i1];
    z[ZIDX(j)]     = y0;
    z[ZIDX(j+m)]   = cmul(y1, w1);
    z[ZIDX(j+2*m)] = cmul(y2, w2);
    z[ZIDX(j+3*m)] = cmul(y3, w3);
  }
  __syncthreads();
}

// Inverse (unscaled): radix-4 DIT with conjugate twiddles, dr input -> natural output.
__device__ __forceinline__ void fft_inv(float2* z, const float2* tw, int t){
  #pragma unroll
  for (int m = 1; m <= 256; m <<= 2){
    __syncthreads();
    int tq = t & (m-1);
    int j  = ((t & ~(m-1)) << 2) | tq;
    int i1 = tq * (256/m);
    float2 w1 = tw[i1], w2 = tw[2*i1], w3 = tw[3*i1];
    float2 a = z[ZIDX(j)];
    float2 b = cmulc(z[ZIDX(j+m)],   w1);
    float2 c = cmulc(z[ZIDX(j+2*m)], w2);
    float2 d = cmulc(z[ZIDX(j+3*m)], w3);
    float t0x=a.x+c.x, t0y=a.y+c.y, t1x=a.x-c.x, t1y=a.y-c.y;
    float t2x=b.x+d.x, t2y=b.y+d.y, t3x=b.x-d.x, t3y=b.y-d.y;
    z[ZIDX(j)]     = make_float2(t0x+t2x, t0y+t2y);
    z[ZIDX(j+2*m)] = make_float2(t0x-t2x, t0y-t2y);
    z[ZIDX(j+m)]   = make_float2(t1x-t3y, t1y+t3x); // t1 + i*t3
    z[ZIDX(j+3*m)] = make_float2(t1x+t3y, t1y-t3x); // t1 - i*t3
  }
  __syncthreads();
}

// ---------------- K2: spectrum magnitudes -> deterministic partials ----------------
__global__ __launch_bounds__(256) void k_spec(const float* __restrict__ x){
  __shared__ float2 z[1088];
  __shared__ float2 tw[1024];
  __shared__ float2 tw2[1025];
  __shared__ float  smean[2048];
  __shared__ float  srstd[2048];
  __shared__ float  acc[1025];
  int t = threadIdx.x;
  int b = blockIdx.y, grp = blockIdx.x;
  for (int i=t;i<1024;i+=256) tw[i]  = g_tw1024[i];
  for (int i=t;i<1025;i+=256){ tw2[i] = g_tw2048[i]; acc[i] = 0.f; }
  for (int i=t;i<2048;i+=256){ smean[i] = g_mean[b*L_+i]; srstd[i] = g_rstd[b*L_+i]; }
  __syncthreads();

  for (int r = 0; r < ROWS_PER_BLK; r++){
    int c = grp*ROWS_PER_BLK + r;
    const float4* rp = (const float4*)(x + ((size_t)(b*C_ + c))*L_);
    float4 v0 = rp[2*t], v1 = rp[2*t+1];
    int l0 = 8*t;
    float n0 = (v0.x - smean[l0+0])*srstd[l0+0];
    float n1 = (v0.y - smean[l0+1])*srstd[l0+1];
    float n2 = (v0.z - smean[l0+2])*srstd[l0+2];
    float n3 = (v0.w - smean[l0+3])*srstd[l0+3];
    float n4 = (v1.x - smean[l0+4])*srstd[l0+4];
    float n5 = (v1.y - smean[l0+5])*srstd[l0+5];
    float n6 = (v1.z - smean[l0+6])*srstd[l0+6];
    float n7 = (v1.w - smean[l0+7])*srstd[l0+7];
    z[ZIDX(4*t+0)] = make_float2(n0,n1);
    z[ZIDX(4*t+1)] = make_float2(n2,n3);
    z[ZIDX(4*t+2)] = make_float2(n4,n5);
    z[ZIDX(4*t+3)] = make_float2(n6,n7);

    fft_fwd(z, tw, t);   // leading sync inside covers the fill

    // unpack real-FFT and accumulate magnitudes
    for (int f = t; f < 512; f += 256){
      if (f == 0){
        float2 z0 = z[ZIDX(0)];
        acc[0]    += fabsf(z0.x + z0.y);      // X[0]
        acc[1024] += fabsf(z0.x - z0.y);      // X[1024]
        float2 zh = z[ZIDX(2)];               // dr4(512)=2 -> X[512]=conj(Z[512])
        acc[512]  += sqrtf(zh.x*zh.x + zh.y*zh.y);
      } else {
        float2 Zf = z[ZIDX(dr4(f))];
        float2 Zg = z[ZIDX(dr4(1024-f))];
        float Ex = 0.5f*(Zf.x + Zg.x), Ey = 0.5f*(Zf.y - Zg.y);
        float Ox = 0.5f*(Zf.y + Zg.y), Oy = -0.5f*(Zf.x - Zg.x);
        float2 W = tw2[f];
        float WOx = Ox*W.x - Oy*W.y, WOy = Ox*W.y + Oy*W.x;
        float Xax = Ex + WOx, Xay = Ey + WOy;   // X[f]
        float Xbx = Ex - WOx, Xby = Ey - WOy;   // conj(X[1024-f]) -> same |.|
        acc[f]      += sqrtf(Xax*Xax + Xay*Xay);
        acc[1024-f] += sqrtf(Xbx*Xbx + Xby*Xby);
      }
    }
    __syncthreads(); // next row overwrites z
  }
  for (int f = t; f < F_; f += 256)
    g_partial[(b*GROUPS + grp)*F_ + f] = acc[f];
}

// ---------------- K3: gating (one block per batch) ----------------
__global__ __launch_bounds__(256) void k_gate(const float* __restrict__ bb,
                                              const float* __restrict__ gw,
                                              const float* __restrict__ gb){
  __shared__ float sgi[1025];
  __shared__ float sred[NE][8];
  __shared__ float ssc[NE];
  __shared__ int   sidx[NE+1];
  int t = threadIdx.x, b = blockIdx.x;
  for (int f = t; f < F_; f += 256){
    float s = 0.f;
    for (int g = 0; g < GROUPS; g++) s += g_partial[(b*GROUPS + g)*F_ + f];
    sgi[f] = s * (1.0f/C_);
  }
  __syncthreads();
  float pe[NE];
  #pragma unroll
  for (int e=0;e<NE;e++) pe[e]=0.f;
  for (int f = t; f < F_; f += 256){
    float gi = sgi[f];
    #pragma unroll
    for (int e=0;e<NE;e++) pe[e] += gi * gw[e*F_ + f];
  }
  #pragma unroll
  for (int e=0;e<NE;e++){
    float v = pe[e];
    #pragma unroll
    for (int o=16;o;o>>=1) v += __shfl_xor_sync(0xffffffffu, v, o);
    if ((t&31)==0) sred[e][t>>5] = v;
  }
  __syncthreads();
  if (t < NE){
    float s = 0.f;
    #pragma unroll
    for (int w=0;w<8;w++) s += sred[t][w];
    ssc[t] = s + gb[t];
  }
  __syncthreads();
  if (t == 0){
    float lg[NE]; float mx = -1e30f;
    for (int e=0;e<NE;e++){ lg[e]=ssc[e]; mx = fmaxf(mx, lg[e]); }
    float sum=0.f;
    for (int e=0;e<NE;e++){ lg[e] = expf(lg[e]-mx); sum += lg[e]; }
    float inv = 1.0f/sum;
    for (int e=0;e<NE;e++) ssc[e] = lg[e]*inv;
    float bnd[NE-1];
    for (int i=0;i<NE-1;i++) bnd[i] = 1.0f/(1.0f + expf(-bb[i]));
    for (int i=1;i<NE-1;i++){            // ascending insertion sort
      float key = bnd[i]; int k=i-1;
      while (k>=0 && bnd[k]>key){ bnd[k+1]=bnd[k]; k--; }
      bnd[k+1]=key;
    }
    sidx[0]=0;
    for (int i=0;i<NE-1;i++) sidx[i+1] = (int)(bnd[i]*(float)F_);
    sidx[NE]=F_;
  }
  __syncthreads();
  for (int f = t; f < F_; f += 256){
    float w = 0.f;
    #pragma unroll
    for (int e=0;e<NE;e++)
      if (f >= sidx[e] && f < sidx[e+1]) w += ssc[e];
    g_w[b*F_ + f] = w;
  }
}

// ---------------- K4: fwd FFT -> filter -> inv FFT -> denorm ----------------
__global__ __launch_bounds__(256) void k_main(const float* __restrict__ x,
                                              float* __restrict__ out){
  __shared__ float2 z[1088];
  __shared__ float2 tw[1024];
  __shared__ float2 tw2[1025];
  __shared__ float  smean[2048];
  __shared__ float  srstd[2048];
  __shared__ float  sw[1025];
  int t = threadIdx.x;
  int b = blockIdx.y, grp = blockIdx.x;
  for (int i=t;i<1024;i+=256) tw[i]  = g_tw1024[i];
  for (int i=t;i<1025;i+=256){ tw2[i] = g_tw2048[i]; sw[i] = g_w[b*F_+i]; }
  for (int i=t;i<2048;i+=256){ smean[i] = g_mean[b*L_+i]; srstd[i] = g_rstd[b*L_+i]; }
  __syncthreads();

  const float sc = 1.0f/2048.0f;  // 1/2 (pack) * 1/1024 (ifft)
  for (int r = 0; r < ROWS_PER_BLK; r++){
    int c = grp*ROWS_PER_BLK + r;
    size_t rowoff = ((size_t)(b*C_ + c))*L_;
    const float4* rp = (const float4*)(x + rowoff);
    float4 v0 = rp[2*t], v1 = rp[2*t+1];
    int l0 = 8*t;
    float n0 = (v0.x - smean[l0+0])*srstd[l0+0];
    float n1 = (v0.y - smean[l0+1])*srstd[l0+1];
    float n2 = (v0.z - smean[l0+2])*srstd[l0+2];
    float n3 = (v0.w - smean[l0+3])*srstd[l0+3];
    float n4 = (v1.x - smean[l0+4])*srstd[l0+4];
    float n5 = (v1.y - smean[l0+5])*srstd[l0+5];
    float n6 = (v1.z - smean[l0+6])*srstd[l0+6];
    float n7 = (v1.w - smean[l0+7])*srstd[l0+7];
    z[ZIDX(4*t+0)] = make_float2(n0,n1);
    z[ZIDX(4*t+1)] = make_float2(n2,n3);
    z[ZIDX(4*t+2)] = make_float2(n4,n5);
    z[ZIDX(4*t+3)] = make_float2(n6,n7);

    fft_fwd(z, tw, t);

    // unpack -> Y = w * X -> repack Z' (scaled by 1/2048), in place
    for (int f = t; f < 512; f += 256){
      if (f == 0){
        float2 z0 = z[ZIDX(0)];
        float X0 = z0.x + z0.y, X1 = z0.x - z0.y;
        float Y0 = sw[0]*X0,   Y1 = sw[1024]*X1;
        z[ZIDX(0)] = make_float2(sc*(Y0+Y1), sc*(Y0-Y1));
        float wh = sw[512]*(1.0f/1024.0f);       // Z'[512] = conj(Y512)/1024 = (w/1024)*Z[512]
        float2 zh = z[ZIDX(2)];
        z[ZIDX(2)] = make_float2(zh.x*wh, zh.y*wh);
      } else {
        int pa = ZIDX(dr4(f)), pb = ZIDX(dr4(1024-f));
        float2 Zf = z[pa], Zg = z[pb];
        float Ex = 0.5f*(Zf.x + Zg.x), Ey = 0.5f*(Zf.y - Zg.y);
        float Ox = 0.5f*(Zf.y + Zg.y), Oy = -0.5f*(Zf.x - Zg.x);
        float2 W = tw2[f];
        float WOx = Ox*W.x - Oy*W.y, WOy = Ox*W.y + Oy*W.x;
        float wa = sw[f], wb = sw[1024-f];
        float Yax = wa*(Ex + WOx), Yay = wa*(Ey + WOy);            // Y[f]
        float Ybx = wb*(Ex - WOx), Yby = wb*(-(Ey - WOy));         // Y[1024-f]
        // Z'[f] = sc * [(Ya + conj(Yb)) + i * conj(W2048^f) * (Ya - conj(Yb))]
        float Ax = Yax + Ybx, Ay = Yay - Yby;
        float Bx = Yax - Ybx, By = Yay + Yby;
        float Cx = Bx*W.x + By*W.y, Cy = By*W.x - Bx*W.y;          // B * conj(W)
        z[pa] = make_float2(sc*(Ax - Cy), sc*(Ay + Cx));
        // Z'[1024-f], with conj(W2048^{1024-f})
        float A2x = Ybx + Yax, A2y = Yby - Yay;
        float B2x = Ybx - Yax, B2y = Yby + Yay;
        float2 W2v = tw2[1024-f];
        float C2x = B2x*W2v.x + B2y*W2v.y, C2y = B2y*W2v.x - B2x*W2v.y;
        z[pb] = make_float2(sc*(A2x - C2y), sc*(A2y + C2x));
      }
    }

    fft_inv(z, tw, t);   // leading sync inside covers the repack writes

    // de-normalize and store
    float2 z0v = z[ZIDX(4*t+0)], z1v = z[ZIDX(4*t+1)];
    float2 z2v = z[ZIDX(4*t+2)], z3v = z[ZIDX(4*t+3)];
    float4 o0, o1;
    o0.x = __fdividef(z0v.x, srstd[l0+0]) + smean[l0+0];
    o0.y = __fdividef(z0v.y, srstd[l0+1]) + smean[l0+1];
    o0.z = __fdividef(z1v.x, srstd[l0+2]) + smean[l0+2];
    o0.w = __fdividef(z1v.y, srstd[l0+3]) + smean[l0+3];
    o1.x = __fdividef(z2v.x, srstd[l0+4]) + smean[l0+4];
    o1.y = __fdividef(z2v.y, srstd[l0+5]) + smean[l0+5];
    o1.z = __fdividef(z3v.x, srstd[l0+6]) + smean[l0+6];
    o1.w = __fdividef(z3v.y, srstd[l0+7]) + smean[l0+7];
    float4* op = (float4*)(out + rowoff);
    op[2*t]   = o0;
    op[2*t+1] = o1;
    // no extra sync needed: next fill writes only this thread's own quartet,
    // and fft_fwd's leading __syncthreads orders it against other threads.
  }
}

// ---------------- launch ----------------
extern "C" void kernel_launch(void* const* d_in, const int* in_sizes, int n_in,
                              void* d_out, int out_size){
  const float* x  = (const float*)d_in[0];
  const float* bb = (const float*)d_in[1];
  const float* gw = (const float*)d_in[2];
  const float* gb = (const float*)d_in[3];
  float* out = (float*)d_out;

  k_twiddle<<<9, 256>>>();
  k_stats<<<dim3(L_/256, B_), 256>>>(x);
  k_spec<<<dim3(GROUPS, B_), 256>>>(x);
  k_gate<<<B_, 256>>>(bb, gw, gb);
  k_main<<<dim3(GROUPS, B_), 256>>>(x, out);
}

// round 2
// speedup vs baseline: 2.3102x; 2.3102x over previous
#include <cuda_runtime.h>

#define B_ 32
#define C_ 512
#define L_ 2048
#define F_ 1025
#define NE 8
#define GROUPS 64          // blocks per batch; each block does 8 rows
#define TPB 128            // 2 row-slots x 64 threads

// ---------------- static device scratch ----------------
__device__ float2 g_tw1024[1024];     // e^{-2*pi*i*j/1024}
__device__ float2 g_tw2048[1025];     // e^{-2*pi*i*f/2048}
__device__ float  g_mean[B_*L_];
__device__ float  g_rstd[B_*L_];
__device__ float  g_partial[B_*GROUPS*F_];
__device__ float  g_lp[B_*8*NE];
__device__ float  g_w[B_*F_];

// ---------------- complex helpers ----------------
__device__ __forceinline__ float2 cmul(float2 a, float2 b){
  return make_float2(a.x*b.x - a.y*b.y, a.x*b.y + a.y*b.x);
}
__device__ __forceinline__ float2 cadd(float2 a, float2 b){ return make_float2(a.x+b.x, a.y+b.y); }
__device__ __forceinline__ float2 csub(float2 a, float2 b){ return make_float2(a.x-b.x, a.y-b.y); }
__device__ __forceinline__ float2 cmnegi(float2 a){ return make_float2(a.y, -a.x); } // *(-i)

__device__ __forceinline__ int br2(int x){ return ((x&1)<<1)|(x>>1); }
// spectrum storage slot for frequency f (see layout derivation):
// f = k1 + 16*k2a + 256*kb ; thread 4*k1+br2(kb) stores reg k2a at [k2a*66 + threadInGroup]
__device__ __forceinline__ int slotf(int f){
  return ((f>>4)&15)*66 + ((f&15)<<2) + br2(f>>8);
}

// in-register forward 16-point DFT (natural in, natural out), W16 = e^{-2pi i/16}
__device__ __forceinline__ void dft16(float2* a){
  const float C1 = 0.92387953251128674f, S1 = 0.38268343236508977f, R2 = 0.70710678118654752f;
  float2 v[16];
  #pragma unroll
  for (int ja=0; ja<4; ja++){
    float2 p0=a[ja], p1=a[ja+4], p2=a[ja+8], p3=a[ja+12];
    float2 t0=cadd(p0,p2), t1=csub(p0,p2), t2=cadd(p1,p3), t3=csub(p1,p3);
    v[ja*4+0]=cadd(t0,t2);
    v[ja*4+1]=make_float2(t1.x+t3.y, t1.y-t3.x);   // t1 - i t3
    v[ja*4+2]=csub(t0,t2);
    v[ja*4+3]=make_float2(t1.x-t3.y, t1.y+t3.x);   // t1 + i t3
  }
  const float2 W1=make_float2( C1,-S1), W2=make_float2( R2,-R2), W3=make_float2( S1,-C1),
               W6=make_float2(-R2,-R2), W9=make_float2(-C1, S1);
  v[5]=cmul(v[5],W1);   v[6]=cmul(v[6],W2);   v[7]=cmul(v[7],W3);
  v[9]=cmul(v[9],W2);   v[10]=cmnegi(v[10]);  v[11]=cmul(v[11],W6);
  v[13]=cmul(v[13],W3); v[14]=cmul(v[14],W6); v[15]=cmul(v[15],W9);
  #pragma unroll
  for (int k=0;k<4;k++){
    float2 p0=v[k], p1=v[4+k], p2=v[8+k], p3=v[12+k];
    float2 t0=cadd(p0,p2), t1=csub(p0,p2), t2=cadd(p1,p3), t3=csub(p1,p3);
    a[k]    =cadd(t0,t2);
    a[k+4]  =make_float2(t1.x+t3.y, t1.y-t3.x);
    a[k+8]  =csub(t0,t2);
    a[k+12] =make_float2(t1.x-t3.y, t1.y+t3.x);
  }
}

// p[k] = w^k for k=0..15, log-depth ladder (max 3 chained cmuls)
__device__ __forceinline__ void build_pows(float2 w, float2* p){
  p[0]=make_float2(1.f,0.f); p[1]=w;
  p[2]=cmul(w,w); p[3]=cmul(p[2],w); p[4]=cmul(p[2],p[2]);
  p[5]=cmul(p[4],p[1]); p[6]=cmul(p[4],p[2]); p[7]=cmul(p[4],p[3]);
  p[8]=cmul(p[4],p[4]);
  #pragma unroll
  for (int k=9;k<16;k++) p[k]=cmul(p[8],p[k-8]);
}

__device__ __forceinline__ float2 shflx(float2 v, int m){
  float2 o;
  o.x = __shfl_xor_sync(0xffffffffu, v.x, m);
  o.y = __shfl_xor_sync(0xffffffffu, v.y, m);
  return o;
}

// Forward 1024-pt complex FFT. Input: a[j] = z[64*j + r] (natural).
// Output: a[k2a] = Z[k1 + 16*k2a + 256*br2(q)] with k1=r>>2, q=r&3.
// Uses T (>=1056 float2, stride-66 layout) as transpose scratch; 2 block syncs.
__device__ __forceinline__ void fft1024(float2* a, float2* T, int r, float2 wr, float2 wq){
  float2 p[16];
  dft16(a);                                    // over j  -> index k1
  build_pows(wr, p);                           // wr = W1024^r
  #pragma unroll
  for (int k=1;k<16;k++) a[k]=cmul(a[k],p[k]); // * W1024^{r*k1}
  #pragma unroll
  for (int k=0;k<16;k++) T[k*66+r]=a[k];
  __syncthreads();
  int k1=r>>2, q=r&3;
  #pragma unroll
  for (int m=0;m<16;m++) a[m]=T[k1*66+4*m+q];  // gather r=4m+q for fixed k1
  __syncthreads();                             // T dead after this
  dft16(a);                                    // over m -> index k2a
  build_pows(wq, p);                           // wq = W64^q
  #pragma unroll
  for (int k=1;k<16;k++) a[k]=cmul(a[k],p[k]); // * W64^{q*k2a}
  bool b2=(q&2)!=0, b1=(q&1)!=0, b3=(q==3);
  #pragma unroll
  for (int k=0;k<16;k++){                      // radix-4 across lane quad
    float2 v=a[k];
    float2 pp=shflx(v,2);
    float2 A = b2 ? csub(pp,v) : cadd(v,pp);
    A = b3 ? cmnegi(A) : A;
    float2 p2=shflx(A,1);
    a[k] = b1 ? csub(p2,A) : cadd(A,p2);
  }
}

// ---------------- K0: twiddle tables ----------------
__global__ void k_twiddle(){
  int j = blockIdx.x*blockDim.x + threadIdx.x;
  if (j < 1024){
    double s, c; sincospi(-2.0*(double)j/1024.0, &s, &c);
    g_tw1024[j] = make_float2((float)c, (float)s);
  }
  if (j < 1025){
    double s, c; sincospi(-(double)j/1024.0, &s, &c);
    g_tw2048[j] = make_float2((float)c, (float)s);
  }
}

// ---------------- K1: per-(b,l) stats over channels ----------------
__global__ __launch_bounds__(256) void k_stats(const float* __restrict__ x){
  int l = blockIdx.x*256 + threadIdx.x;
  int b = blockIdx.y;
  const float* p = x + (size_t)b*C_*L_ + l;
  float s = 0.f, s2 = 0.f;
  #pragma unroll 8
  for (int c = 0; c < C_; c++){
    float v = p[(size_t)c*L_];
    s += v; s2 += v*v;
  }
  float mean = s * (1.0f/C_);
  float var  = (s2 - s*s*(1.0f/C_)) * (1.0f/(C_-1)) + 1e-5f;
  g_mean[b*L_+l] = mean;
  g_rstd[b*L_+l] = rsqrtf(var);
}

// ---------------- K2: spectra -> |X| partial sums ----------------
__global__ __launch_bounds__(TPB) void k_spec(const float* __restrict__ x){
  extern __shared__ float2 smraw[];
  float2* T   = smraw;            // 2*1088
  float2* m2  = T + 2176;         // 1024
  float2* r2v = m2 + 1024;        // 1024
  float*  acc = (float*)(r2v + 1024); // 1025
  int t=threadIdx.x, s=t>>6, r=t&63;
  int b=blockIdx.y, grp=blockIdx.x;
  float2* Ts = T + s*1088;
  const float2* gm2=(const float2*)(g_mean + b*L_);
  const float2* gr2=(const float2*)(g_rstd + b*L_);
  for (int i=t;i<1024;i+=TPB){ m2[i]=gm2[i]; r2v[i]=gr2[i]; }
  for (int i=t;i<F_;i+=TPB) acc[i]=0.f;
  float2 wr=g_tw1024[r];
  float2 wq=g_tw1024[(r&3)<<4];
  __syncthreads();

  for (int it=0; it<4; it++){
    int c = grp*8 + it*2 + s;
    const float2* xr = (const float2*)(x + ((size_t)(b*C_+c))*L_);
    float2 a[16];
    #pragma unroll
    for (int j=0;j<16;j++){
      int n=(j<<6)+r;
      float2 v=xr[n], mm=m2[n], rr=r2v[n];
      a[j]=make_float2((v.x-mm.x)*rr.x,(v.y-mm.y)*rr.y);
    }
    fft1024(a, Ts, r, wr, wq);
    #pragma unroll
    for (int k=0;k<16;k++) Ts[k*66+r]=a[k];   // store spectrum (safe: transpose reads done)
    __syncthreads();

    // real-FFT unpack + |X| accumulate (both slots, all 128 threads)
    #pragma unroll
    for (int i=0;i<4;i++){
      int f = t + (i<<7);                     // [0,512)
      if (f==0){
        #pragma unroll
        for (int s2=0;s2<2;s2++){
          float2 z0=T[s2*1088 + 0];
          acc[0]    += fabsf(z0.x+z0.y);
          acc[1024] += fabsf(z0.x-z0.y);
          float2 zh=T[s2*1088 + 1];           // slotf(512)=1
          acc[512]  += sqrtf(zh.x*zh.x+zh.y*zh.y);
        }
      } else {
        int pa=slotf(f), pb=slotf(1024-f);
        float2 W=g_tw2048[f];
        float sa=0.f, sb=0.f;
        #pragma unroll
        for (int s2=0;s2<2;s2++){
          float2 Zf=T[s2*1088+pa], Zg=T[s2*1088+pb];
          float Ex=0.5f*(Zf.x+Zg.x), Ey=0.5f*(Zf.y-Zg.y);
          float Ox=0.5f*(Zf.y+Zg.y), Oy=-0.5f*(Zf.x-Zg.x);
          float WOx=Ox*W.x-Oy*W.y, WOy=Ox*W.y+Oy*W.x;
          float Xax=Ex+WOx, Xay=Ey+WOy;
          float Xbx=Ex-WOx, Xby=Ey-WOy;
          sa += sqrtf(Xax*Xax+Xay*Xay);
          sb += sqrtf(Xbx*Xbx+Xby*Xby);
        }
        acc[f]      += sa;
        acc[1024-f] += sb;
      }
    }
    __syncthreads();
  }
  for (int f=t; f<F_; f+=TPB)
    g_partial[(b*GROUPS+grp)*F_+f] = acc[f];
}

// ---------------- K3a: reduce partials + partial logits ----------------
__global__ __launch_bounds__(256) void k_gate1(const float* __restrict__ gw){
  __shared__ float sgi[F_];
  __shared__ float sred[NE][8];
  int t=threadIdx.x, b=blockIdx.x, sl=blockIdx.y;
  for (int f=t; f<F_; f+=256){
    float s=0.f;
    #pragma unroll
    for (int g=0; g<8; g++) s += g_partial[(b*GROUPS + sl*8 + g)*F_ + f];
    sgi[f]=s;
  }
  __syncthreads();
  float pe[NE];
  #pragma unroll
  for (int e=0;e<NE;e++) pe[e]=0.f;
  for (int f=t; f<F_; f+=256){
    float gi=sgi[f];
    #pragma unroll
    for (int e=0;e<NE;e++) pe[e]+=gi*gw[e*F_+f];
  }
  #pragma unroll
  for (int e=0;e<NE;e++){
    float v=pe[e];
    #pragma unroll
    for (int o=16;o;o>>=1) v += __shfl_xor_sync(0xffffffffu, v, o);
    if ((t&31)==0) sred[e][t>>5]=v;
  }
  __syncthreads();
  if (t < NE){
    float s=0.f;
    #pragma unroll
    for (int w=0;w<8;w++) s += sred[t][w];
    g_lp[(b*8+sl)*NE + t] = s;
  }
}

// ---------------- K3b: softmax + bands -> per-bin weights ----------------
__global__ __launch_bounds__(128) void k_gate2(const float* __restrict__ bb,
                                               const float* __restrict__ gb){
  __shared__ float ssc[NE];
  __shared__ int   sidx[NE+1];
  int t=threadIdx.x, b=blockIdx.x;
  if (t==0){
    float lg[NE]; float mx=-1e30f;
    for (int e=0;e<NE;e++){
      float s=0.f;
      for (int sl=0; sl<8; sl++) s += g_lp[(b*8+sl)*NE + e];
      lg[e]=s*(1.0f/C_)+gb[e];
      mx=fmaxf(mx,lg[e]);
    }
    float sum=0.f;
    for (int e=0;e<NE;e++){ lg[e]=expf(lg[e]-mx); sum+=lg[e]; }
    float inv=1.0f/sum;
    for (int e=0;e<NE;e++) ssc[e]=lg[e]*inv;
    float bnd[NE-1];
    for (int i=0;i<NE-1;i++) bnd[i]=1.0f/(1.0f+expf(-bb[i]));
    for (int i=1;i<NE-1;i++){
      float key=bnd[i]; int k=i-1;
      while (k>=0 && bnd[k]>key){ bnd[k+1]=bnd[k]; k--; }
      bnd[k+1]=key;
    }
    sidx[0]=0;
    for (int i=0;i<NE-1;i++) sidx[i+1]=(int)(bnd[i]*(float)F_);
    sidx[NE]=F_;
  }
  __syncthreads();
  for (int f=t; f<F_; f+=128){
    float w=0.f;
    #pragma unroll
    for (int e=0;e<NE;e++)
      if (f>=sidx[e] && f<sidx[e+1]) w+=ssc[e];
    g_w[b*F_+f]=w;
  }
}

// ---------------- K4: fwd FFT -> filter -> inv FFT -> denorm ----------------
__global__ __launch_bounds__(TPB) void k_main(const float* __restrict__ x,
                                              float* __restrict__ out){
  extern __shared__ float2 smraw[];
  float2* T   = smraw;            // 2*1088 (transpose / spectrum / time staging)
  float2* N   = T + 2176;         // 2*1024 (conj(Z') natural layout)
  float2* m2  = N + 2048;         // 1024
  float2* r2v = m2 + 1024;        // 1024
  float*  sw  = (float*)(r2v + 1024); // 1025
  int t=threadIdx.x, s=t>>6, r=t&63;
  int b=blockIdx.y, grp=blockIdx.x;
  float2* Ts = T + s*1088;
  float2* Nsl = N + s*1024;
  const float2* gm2=(const float2*)(g_mean + b*L_);
  const float2* gr2=(const float2*)(g_rstd + b*L_);
  for (int i=t;i<1024;i+=TPB){ m2[i]=gm2[i]; r2v[i]=gr2[i]; }
  for (int i=t;i<F_;i+=TPB) sw[i]=g_w[b*F_+i];
  float2 wr=g_tw1024[r];
  float2 wq=g_tw1024[(r&3)<<4];
  __syncthreads();

  const float sc = 1.0f/2048.0f;  // 1/2 (real pack) * 1/1024 (ifft)
  for (int it=0; it<4; it++){
    int c = grp*8 + it*2 + s;
    size_t rowoff = ((size_t)(b*C_+c))*L_;
    const float2* xr = (const float2*)(x + rowoff);
    float2 a[16];
    #pragma unroll
    for (int j=0;j<16;j++){
      int n=(j<<6)+r;
      float2 v=xr[n], mm=m2[n], rr=r2v[n];
      a[j]=make_float2((v.x-mm.x)*rr.x,(v.y-mm.y)*rr.y);
    }
    fft1024(a, Ts, r, wr, wq);
    #pragma unroll
    for (int k=0;k<16;k++) Ts[k*66+r]=a[k];   // spectrum store
    __syncthreads();

    // filter: unpack -> Y=w*X -> repack Z' -> write conj(Z') to N (natural order)
    #pragma unroll
    for (int i=0;i<4;i++){
      int f = t + (i<<7);
      if (f==0){
        #pragma unroll
        for (int s2=0;s2<2;s2++){
          float2 z0=T[s2*1088 + 0];
          float X0=z0.x+z0.y, X1=z0.x-z0.y;
          float Y0=sw[0]*X0, Y1=sw[1024]*X1;
          N[s2*1024 + 0]   = make_float2(sc*(Y0+Y1), -sc*(Y0-Y1));
          float wh = sw[512]*(1.0f/1024.0f);
          float2 zh=T[s2*1088 + 1];           // slotf(512)=1
          N[s2*1024 + 512] = make_float2(zh.x*wh, -zh.y*wh);
        }
      } else {
        int pa=slotf(f), pb=slotf(1024-f);
        float wa=sw[f], wb=sw[1024-f];
        float2 W =g_tw2048[f];
        float2 W2=g_tw2048[1024-f];
        #pragma unroll
        for (int s2=0;s2<2;s2++){
          float2 Zf=T[s2*1088+pa], Zg=T[s2*1088+pb];
          float Ex=0.5f*(Zf.x+Zg.x), Ey=0.5f*(Zf.y-Zg.y);
          float Ox=0.5f*(Zf.y+Zg.y), Oy=-0.5f*(Zf.x-Zg.x);
          float WOx=Ox*W.x-Oy*W.y, WOy=Ox*W.y+Oy*W.x;
          float Yax=wa*(Ex+WOx), Yay=wa*(Ey+WOy);
          float Ybx=wb*(Ex-WOx), Yby=wb*(-(Ey-WOy));
          float Ax=Yax+Ybx, Ay=Yay-Yby;
          float Bx=Yax-Ybx, By=Yay+Yby;
          float Cx=Bx*W.x+By*W.y, Cy=By*W.x-Bx*W.y;
          N[s2*1024 + f]      = make_float2(sc*(Ax-Cy), -sc*(Ay+Cx));
          float A2x=Ybx+Yax, A2y=Yby-Yay;
          float B2x=Ybx-Yax, B2y=Yby+Yay;
          float C2x=B2x*W2.x+B2y*W2.y, C2y=B2y*W2.x-B2x*W2.y;
          N[s2*1024 + 1024-f] = make_float2(sc*(A2x-C2y), -sc*(A2y+C2x));
        }
      }
    }
    __syncthreads();

    // inverse FFT via conjugation trick: ifft(Z') = conj(fft(conj(Z')))
    #pragma unroll
    for (int j=0;j<16;j++) a[j]=Nsl[(j<<6)+r];
    fft1024(a, Ts, r, wr, wq);
    // stage time samples (conjugated) into Ts at padded natural index
    {
      int k1=r>>2, kb=br2(r&3);
      int base = k1 + 264*kb;                  // n + 8*(n>>8), n = k1+16k+256kb
      #pragma unroll
      for (int k=0;k<16;k++)
        Ts[base + (k<<4)] = make_float2(a[k].x, -a[k].y);
    }
    __syncthreads();

    // de-normalize + coalesced store
    float4* orow = (float4*)(out + rowoff);
    #pragma unroll
    for (int cc=0; cc<8; cc++){
      int i4 = (cc<<6) + r;                    // float4 index in row
      int n0 = i4<<1;
      int u  = n0 + ((n0>>8)<<3);
      float2 y0=Ts[u], y1=Ts[u+1];
      float2 mm0=m2[n0], mm1=m2[n0+1], rr0=r2v[n0], rr1=r2v[n0+1];
      float4 o;
      o.x=__fdividef(y0.x, rr0.x)+mm0.x;
      o.y=__fdividef(y0.y, rr0.y)+mm0.y;
      o.z=__fdividef(y1.x, rr1.x)+mm1.x;
      o.w=__fdividef(y1.y, rr1.y)+mm1.y;
      orow[i4]=o;
    }
    __syncthreads();
  }
}

// ---------------- launch ----------------
extern "C" void kernel_launch(void* const* d_in, const int* in_sizes, int n_in,
                              void* d_out, int out_size){
  const float* x  = (const float*)d_in[0];
  const float* bb = (const float*)d_in[1];
  const float* gw = (const float*)d_in[2];
  const float* gb = (const float*)d_in[3];
  float* out = (float*)d_out;

  const int SM_SPEC = (2176+1024+1024)*sizeof(float2) + F_*sizeof(float);        // ~37.9KB
  const int SM_MAIN = (2176+2048+1024+1024)*sizeof(float2) + F_*sizeof(float);   // ~54.3KB
  cudaFuncSetAttribute(k_main, cudaFuncAttributeMaxDynamicSharedMemorySize, SM_MAIN);
  cudaFuncSetAttribute(k_spec, cudaFuncAttributeMaxDynamicSharedMemorySize, SM_SPEC);

  k_twiddle<<<9, 256>>>();
  k_stats<<<dim3(L_/256, B_), 256>>>(x);
  k_spec<<<dim3(GROUPS, B_), TPB, SM_SPEC>>>(x);
  k_gate1<<<dim3(B_, 8), 256>>>(gw);
  k_gate2<<<B_, 128>>>(bb, gb);
  k_main<<<dim3(GROUPS, B_), TPB, SM_MAIN>>>(x, out);
}